// round 16
// baseline (speedup 1.0000x reference)
#include <cuda_runtime.h>
#include <math.h>

#define NPTS   8192
#define RROIS  128
#define G3     216
#define MGRID  (RROIS*G3)
#define NXC    252
#define NYC    252
#define NZC    11
#define NCELL  (NXC*NYC*NZC)      // 698544
#define CAP    8
#define CMID   64
#define CIN    32
#define CK     35
#define FCH    256

// ------------------------- scratch -------------------------
__device__ int    g_cellcnt[NCELL];        // zero-init at load; reset blocks in k_mlp restore invariant
__device__ float4 g_cellpts[NCELL*CAP];    // (x,y,z, bitcast(index))
__device__ int    g_nsamp;
__device__ int    g_slist[MGRID*16];       // sample pair list: gw*16+s
__device__ int    g_gcnt[G3];
__device__ int    g_glist[G3*RROIS];
__device__ int    g_qcnt[MGRID];
__device__ int    g_qidx[MGRID*16];
__device__ float  g_newxyz[MGRID*3];
__device__ float  g_delta[MGRID*CMID];     // holds pooled max (>=0), zeroed per-cell in query
__device__ float  g_w0t[G3*CMID*FCH];      // [g*64+c][o], o contiguous
__device__ float  g_bpart[G3*FCH];         // per-col-tile pe-weighted partial sums
__device__ float  g_base[FCH];
__device__ float  g_pe[CMID];
__device__ float  g_x[RROIS*FCH];          // zeroed in prepA; atomically accumulated
__device__ float  g_wT[7*FCH*FCH];         // packed: [mat][k4][o][ki]

#define BN_INV 0.9999949932f

__device__ __forceinline__ int cellOf(int ix,int iy,int iz){ return (ix*NYC+iy)*NZC+iz; }

// ------------------------- pe: empty-cell pooled vector (side stream, 1 block) -------------------------
__global__ void k_pe(const float* __restrict__ w1, const float* __restrict__ g1v,
                     const float* __restrict__ b1v, const float* __restrict__ b0v){
  __shared__ float h0e[CMID];
  int t = threadIdx.x;
  h0e[t] = fmaxf(b0v[t], 0.f);
  __syncthreads();
  float acc = 0.f;
  #pragma unroll 8
  for (int j=0;j<CMID;j++) acc += h0e[j]*w1[t*CMID+j];
  g_pe[t] = fmaxf(g1v[t]*acc*BN_INV + b1v[t], 0.f);
}

// ------------------------- prep A: w0t transpose + bpart partials + zero g_x -------------------------
__global__ void k_prepA(const float* __restrict__ sw0){
  __shared__ float sh[64*65];
  __shared__ float pe_w[64];
  __shared__ float red[256];
  int b = blockIdx.x, tid = threadIdx.x;
  int tx = tid & 15, ty = tid >> 4;
  if (b < 864){
    int ct = b % 216, ot = b / 216;
    int col0 = ct*64, o0 = ot*64;
    if (tid < 64) pe_w[tid] = g_pe[(col0+tid)/216];
    #pragma unroll
    for (int i=0;i<4;i++){
      int r = ty + 16*i;
      float4 v = *(const float4*)&sw0[(size_t)(o0+r)*13824 + col0 + 4*tx];
      float* t = &sh[r*65 + 4*tx];
      t[0]=v.x; t[1]=v.y; t[2]=v.z; t[3]=v.w;
    }
    __syncthreads();
    #pragma unroll
    for (int i=0;i<4;i++){
      int ci = ty + 16*i;
      int col = col0 + ci;
      int c = col / 216, g = col - c*216;
      float4 v;
      v.x = sh[(4*tx+0)*65 + ci];
      v.y = sh[(4*tx+1)*65 + ci];
      v.z = sh[(4*tx+2)*65 + ci];
      v.w = sh[(4*tx+3)*65 + ci];
      *(float4*)&g_w0t[(g*CMID + c)*FCH + o0 + 4*tx] = v;
    }
    // pe-weighted partial sum for base
    int ol = tid & 63, q = tid >> 6;
    float s = 0.f;
    #pragma unroll
    for (int ci=0; ci<16; ci++) s += sh[ol*65 + q*16+ci]*pe_w[q*16+ci];
    red[tid] = s;
    __syncthreads();
    if (q == 0)
      g_bpart[ct*FCH + o0 + ol] = red[ol] + red[64+ol] + red[128+ol] + red[192+ol];
  } else {
    int d = b - 864;               // 32 blocks zero g_x
    int4 z = make_int4(0,0,0,0);
    for (int i = d*256 + tid; i < RROIS*FCH/4; i += 32*256)
      ((int4*)g_x)[i] = z;
  }
}

// ------------------------- prep B: head-matrix pack + base reduce -------------------------
__global__ void k_prepB(const float* __restrict__ m0,const float* __restrict__ m1,
                        const float* __restrict__ m2,const float* __restrict__ m3,
                        const float* __restrict__ m4,const float* __restrict__ m5,
                        const float* __restrict__ m6){
  __shared__ float sh[64*65];
  int b = blockIdx.x, tid = threadIdx.x;
  int tx = tid & 15, ty = tid >> 4;
  if (b < 112){
    int mat = b >> 4, tt = b & 15;
    int kt = tt & 3, ot = tt >> 2;
    const float* W = (mat==0)?m0:(mat==1)?m1:(mat==2)?m2:(mat==3)?m3:(mat==4)?m4:(mat==5)?m5:m6;
    int k0 = kt*64, o0 = ot*64;
    #pragma unroll
    for (int i=0;i<4;i++){
      int r = ty + 16*i;
      float4 v = *(const float4*)&W[(o0+r)*FCH + k0 + 4*tx];
      float* t = &sh[r*65 + 4*tx];
      t[0]=v.x; t[1]=v.y; t[2]=v.z; t[3]=v.w;
    }
    __syncthreads();
    #pragma unroll
    for (int i=0;i<4;i++){
      int idx = tid + 256*i;
      int ol = idx & 63, k4l = idx >> 6;
      float4 v;
      v.x = sh[ol*65 + 4*k4l+0];
      v.y = sh[ol*65 + 4*k4l+1];
      v.z = sh[ol*65 + 4*k4l+2];
      v.w = sh[ol*65 + 4*k4l+3];
      int k4g = (k0>>2) + k4l;
      *(float4*)&g_wT[mat*FCH*FCH + k4g*1024 + (o0+ol)*4] = v;
    }
  } else if (tid < 128){
    // base reduce: base[o] = sum_ct bpart[ct][o]
    int o = (b-112)*128 + tid;
    float s0=0.f, s1=0.f, s2=0.f, s3=0.f;
    #pragma unroll 4
    for (int ct=0; ct<G3; ct+=4){
      s0 += g_bpart[(ct+0)*FCH + o];
      s1 += g_bpart[(ct+1)*FCH + o];
      s2 += g_bpart[(ct+2)*FCH + o];
      s3 += g_bpart[(ct+3)*FCH + o];
    }
    g_base[o] = (s0+s1) + (s2+s3);
  }
}

// ------------------------- hash insert + grid-point precompute + counters -------------------------
__global__ void k_insert(const float* __restrict__ xyz, const float* __restrict__ rois){
  int b = blockIdx.x, tid = threadIdx.x;
  if (b < 32){
    int i = b*256 + tid;
    float x = xyz[3*i], y = xyz[3*i+1], z = xyz[3*i+2];
    int ix = (int)floorf((x+50.f)*2.5f); ix = min(max(ix,0), NXC-1);
    int iy = (int)floorf((y+50.f)*2.5f); iy = min(max(iy,0), NYC-1);
    int iz = (int)floorf((z+ 2.f)*2.5f); iz = min(max(iz,0), NZC-1);
    int cell = cellOf(ix,iy,iz);
    int slot = atomicAdd(&g_cellcnt[cell], 1);
    if (slot < CAP){
      float4 p; p.x=x; p.y=y; p.z=z; p.w=__int_as_float(i);
      g_cellpts[cell*CAP+slot] = p;
    }
  } else if (b == 32){
    if (tid < G3) g_gcnt[tid] = 0;
    if (tid == 255) g_nsamp = 0;
  } else {
    int r = b - 33;                  // one block per roi
    __shared__ float R7[7];
    __shared__ double trg[2];
    if (tid < 7) R7[tid] = rois[r*7+tid];
    if (tid == 7){
      double a = (double)rois[r*7+6];
      trg[0] = cos(a); trg[1] = sin(a);
    }
    __syncthreads();
    if (tid < G3){
      int m = r*G3 + tid;
      int ixg = tid/36, iyg = (tid/6)%6, izg = tid%6;
      float sx=R7[3], sy=R7[4], sz=R7[5];
      float lx = ((float)ixg + 0.5f)/6.0f * sx - 0.5f*sx;
      float ly = ((float)iyg + 0.5f)/6.0f * sy - 0.5f*sy;
      float lz = ((float)izg + 0.5f)/6.0f * sz - 0.5f*sz;
      float cs = (float)trg[0], sn = (float)trg[1];
      g_newxyz[3*m]   = lx*cs - ly*sn + R7[0];
      g_newxyz[3*m+1] = lx*sn + ly*cs + R7[1];
      g_newxyz[3*m+2] = lz + R7[2];
    }
  }
}

// ------------------------- ball query: 8 lanes per grid point, reads precomputed centers -------------------------
__global__ void __launch_bounds__(256) k_query(){
  int t  = blockIdx.x*256 + threadIdx.x;
  int gw = t >> 3;                  // grid-point id
  int l8 = t & 7;
  unsigned mask8 = 0xFFu << (unsigned)(threadIdx.x & 24);

  float px = g_newxyz[3*gw], py = g_newxyz[3*gw+1], pz = g_newxyz[3*gw+2];

  const float RS = 0.4001f;
  int ix0 = max((int)floorf((px-RS+50.f)*2.5f), 0);
  int ix1 = min((int)floorf((px+RS+50.f)*2.5f), NXC-1);
  int iy0 = max((int)floorf((py-RS+50.f)*2.5f), 0);
  int iy1 = min((int)floorf((py+RS+50.f)*2.5f), NYC-1);
  int iz0 = max((int)floorf((pz-RS+ 2.f)*2.5f), 0);
  int iz1 = min((int)floorf((pz+RS+ 2.f)*2.5f), NZC-1);
  int ny = iy1-iy0+1, nz = iz1-iz0+1;
  int ncl = (ix1-ix0+1)*ny*nz;

  int loc[16]; int nloc = 0;
  for (int cidx = l8; cidx < ncl; cidx += 8){
    int a   = cidx/(ny*nz);
    int rem = cidx - a*(ny*nz);
    int cix = ix0 + a;
    int ciy = iy0 + rem/nz;
    int ciz = iz0 + rem - (rem/nz)*nz;
    int cell = cellOf(cix,ciy,ciz);
    int c = min(g_cellcnt[cell], CAP);
    const float4* cp = &g_cellpts[cell*CAP];
    for (int u=0; u<c; u++){
      float4 p = cp[u];
      float dx = p.x-px, dy = p.y-py, dz = p.z-pz;
      if (dx*dx + dy*dy + dz*dz < 0.16f){
        int j = __float_as_int(p.w);
        if (nloc < 16){
          int q = nloc++;
          while (q>0 && loc[q-1]>j){ loc[q]=loc[q-1]; q--; }
          loc[q] = j;
        } else if (j < loc[15]){
          int q = 15;
          while (q>0 && loc[q-1]>j){ loc[q]=loc[q-1]; q--; }
          loc[q] = j;
        }
      }
    }
  }

  unsigned hits = __ballot_sync(0xffffffffu, nloc > 0) & mask8;
  if (hits == 0){
    if (l8 == 0) g_qcnt[gw] = 0;
    return;
  }

  int ptr = 0;
  int head = (nloc > 0) ? loc[0] : 0x7fffffff;
  int cnt = 0;
  #pragma unroll 1
  for (int it=0; it<16; it++){
    int mn = __reduce_min_sync(mask8, head);
    if (mn == 0x7fffffff) break;
    if (l8 == 0) g_qidx[gw*16 + cnt] = mn;
    cnt++;
    if (head == mn){
      ptr++;
      head = (ptr < nloc) ? loc[ptr] : 0x7fffffff;
    }
  }
  int base = 0;
  if (l8 == 0){
    g_qcnt[gw] = cnt;
    int gi = gw % G3, r = gw / G3;
    int s = atomicAdd(&g_gcnt[gi], 1); g_glist[gi*RROIS+s] = r;
    base = atomicAdd(&g_nsamp, cnt);
  }
  base = __shfl_sync(mask8, base, (threadIdx.x & 24));
  for (int s=l8; s<cnt; s+=8) g_slist[base+s] = gw*16+s;
  for (int c=l8; c<CMID; c+=8) g_delta[gw*CMID+c] = 0.f;   // init for atomicMax
}

// ------------------------- point MLP v4: warp per sample + fused cellcnt reset blocks ---------
__global__ void __launch_bounds__(256) k_mlp(
    const float* __restrict__ xyz, const float* __restrict__ feat,
    const float* __restrict__ w0, const float* __restrict__ gg0, const float* __restrict__ bb0,
    const float* __restrict__ w1, const float* __restrict__ gg1, const float* __restrict__ bb1){
  int tid = threadIdx.x;
  if (blockIdx.x >= 296){
    // reset blocks: restore cellcnt zero invariant (runs after query on main stream)
    int i = (blockIdx.x - 296)*256 + tid;
    if (i < NPTS){
      float x = xyz[3*i], y = xyz[3*i+1], z = xyz[3*i+2];
      int ix = (int)floorf((x+50.f)*2.5f); ix = min(max(ix,0), NXC-1);
      int iy = (int)floorf((y+50.f)*2.5f); iy = min(max(iy,0), NYC-1);
      int iz = (int)floorf((z+ 2.f)*2.5f); iz = min(max(iz,0), NZC-1);
      g_cellcnt[cellOf(ix,iy,iz)] = 0;
    }
    return;
  }
  int wid = tid >> 5, lane = tid & 31;
  __shared__ __align__(16) float sw0s[CMID*CK];     // 8.96KB
  __shared__ float sw1s[CMID*65];                   // 16.6KB
  __shared__ float sg0[CMID], sb0[CMID], sg1[CMID], sb1[CMID];

  const float4* w04 = (const float4*)w0;
  for (int e=tid; e<560; e+=256) ((float4*)sw0s)[e] = w04[e];
  const float4* w14 = (const float4*)w1;
  for (int e=tid; e<1024; e+=256){
    float4 v = w14[e];
    int c = e>>4, j0 = (e&15)*4;
    float* p = &sw1s[c*65 + j0];
    p[0]=v.x; p[1]=v.y; p[2]=v.z; p[3]=v.w;
  }
  if (tid < 64){
    sg0[tid]=gg0[tid]; sb0[tid]=bb0[tid]; sg1[tid]=gg1[tid]; sb1[tid]=bb1[tid];
  }
  __syncthreads();

  int ch0 = lane, ch1 = lane + 32;
  float g0a=sg0[ch0], b0a=sb0[ch0], g0b=sg0[ch1], b0b=sb0[ch1];
  float g1a=sg1[ch0], b1a=sb1[ch0], g1b=sg1[ch1], b1b=sb1[ch1];
  int nsamp = g_nsamp;

  for (int p = blockIdx.x*8 + wid; p < nsamp; p += 296*8){
    int e = g_slist[p];
    int m = e >> 4;
    int j = g_qidx[e];
    float nx=g_newxyz[3*m], ny=g_newxyz[3*m+1], nz=g_newxyz[3*m+2];
    float v, ve = 0.f;
    if (lane < 3) v = xyz[3*j+lane] - ((lane==0)?nx:((lane==1)?ny:nz));
    else          v = feat[j*CIN + lane-3];
    if (lane < 3) ve = feat[j*CIN + 29 + lane];
    float a0=0.f, a1=0.f;
    #pragma unroll
    for (int k=0;k<32;k++){
      float x = __shfl_sync(0xffffffffu, v, k);
      a0 += x*sw0s[ch0*CK+k];
      a1 += x*sw0s[ch1*CK+k];
    }
    #pragma unroll
    for (int k=0;k<3;k++){
      float x = __shfl_sync(0xffffffffu, ve, k);
      a0 += x*sw0s[ch0*CK+32+k];
      a1 += x*sw0s[ch1*CK+32+k];
    }
    float h0a = fmaxf(g0a*a0*BN_INV + b0a, 0.f);
    float h0b = fmaxf(g0b*a1*BN_INV + b0b, 0.f);
    float c0=0.f, c1=0.f;
    #pragma unroll
    for (int jj=0;jj<32;jj++){
      float hv = __shfl_sync(0xffffffffu, h0a, jj);
      c0 += hv*sw1s[ch0*65+jj];
      c1 += hv*sw1s[ch1*65+jj];
    }
    #pragma unroll
    for (int jj=0;jj<32;jj++){
      float hv = __shfl_sync(0xffffffffu, h0b, jj);
      c0 += hv*sw1s[ch0*65+32+jj];
      c1 += hv*sw1s[ch1*65+32+jj];
    }
    float o0 = fmaxf(g1a*c0*BN_INV + b1a, 0.f);
    float o1 = fmaxf(g1b*c1*BN_INV + b1b, 0.f);
    atomicMax((unsigned*)g_delta + (m*CMID + ch0), __float_as_uint(o0));
    atomicMax((unsigned*)g_delta + (m*CMID + ch1), __float_as_uint(o1));
  }
}

// ------------------------- sparse scatter: block per (grid-cell, o-half), 2 rois/iter -------------------------
__global__ void __launch_bounds__(128) k_sh0g(){
  int b = blockIdx.x;
  int g = b >> 1, half = b & 1;
  int tid = threadIdx.x;
  int ng = g_gcnt[g];
  if (ng == 0) return;
  __shared__ __align__(16) float sw[CMID*128];   // 32KB
  __shared__ float sd0[CMID], sd1[CMID], spe[CMID];
  const float4* s4 = (const float4*)g_w0t;
  float4* sw4 = (float4*)sw;
  for (int i=tid; i<2048; i+=128){
    int c = i >> 5, o4 = i & 31;
    sw4[c*32 + o4] = s4[(size_t)(g*CMID + c)*64 + half*32 + o4];
  }
  if (tid < CMID) spe[tid] = g_pe[tid];
  __syncthreads();
  int o = half*128 + tid;
  for (int t=0; t<ng; t+=2){
    int r0 = g_glist[g*RROIS + t];
    int r1 = (t+1<ng)? g_glist[g*RROIS + t+1] : -1;
    if (tid < CMID)                sd0[tid]    = g_delta[(r0*G3+g)*CMID + tid]    - spe[tid];
    else if (r1 >= 0)              sd1[tid-64] = g_delta[(r1*G3+g)*CMID + tid-64] - spe[tid-64];
    __syncthreads();
    float a0 = 0.f, a1 = 0.f;
    #pragma unroll 16
    for (int c=0;c<CMID;c++){
      float wv = sw[c*128 + tid];
      a0 += sd0[c]*wv;
      a1 += sd1[c]*wv;
    }
    atomicAdd(&g_x[r0*FCH + o], a0);
    if (r1 >= 0) atomicAdd(&g_x[r1*FCH + o], a1);
    __syncthreads();
  }
}

// ------------------------- fused head MLPs, 4 rois per block -------------------------
__device__ __forceinline__ void layer4(int mat, float X[4][FCH], float Y[4][FCH], int t){
  const float4* P  = (const float4*)&g_wT[mat*FCH*FCH];
  const float4* x0 = (const float4*)X[0];
  const float4* x1 = (const float4*)X[1];
  const float4* x2 = (const float4*)X[2];
  const float4* x3 = (const float4*)X[3];
  float a0=0.f,a1=0.f,a2=0.f,a3=0.f;
  #pragma unroll 8
  for (int k4=0;k4<64;k4++){
    float4 w = P[k4*FCH + t];
    float4 v0=x0[k4], v1=x1[k4], v2=x2[k4], v3=x3[k4];
    a0 += w.x*v0.x + w.y*v0.y + w.z*v0.z + w.w*v0.w;
    a1 += w.x*v1.x + w.y*v1.y + w.z*v1.z + w.w*v1.w;
    a2 += w.x*v2.x + w.y*v2.y + w.z*v2.z + w.w*v2.w;
    a3 += w.x*v3.x + w.y*v3.y + w.z*v3.z + w.w*v3.w;
  }
  Y[0][t]=fmaxf(a0,0.f); Y[1][t]=fmaxf(a1,0.f);
  Y[2][t]=fmaxf(a2,0.f); Y[3][t]=fmaxf(a3,0.f);
  __syncthreads();
}

__global__ void __launch_bounds__(256) k_heads(
    const float* __restrict__ cw2,const float* __restrict__ cb2,
    const float* __restrict__ iw2,const float* __restrict__ ib2,
    const float* __restrict__ rw2,const float* __restrict__ rb2,
    float* __restrict__ out){
  __shared__ __align__(16) float X[4][FCH], Y[4][FCH];
  int t = threadIdx.x;
  int rb = blockIdx.x*4, h = blockIdx.y;
  float base = g_base[t];
  #pragma unroll
  for (int rr=0; rr<4; rr++) X[rr][t] = fmaxf(g_x[(rb+rr)*FCH + t] + base, 0.f);
  __syncthreads();
  layer4(0,     X, Y, t);     // shared_w1
  layer4(1+2*h, Y, X, t);     // head layer 0
  layer4(2+2*h, X, Y, t);     // head layer 1
  const float* w2 = (h==0)? cw2 : (h==1)? iw2 : rw2;
  const float* b2 = (h==0)? cb2 : (h==1)? ib2 : rb2;
  int nq  = (h==2)? 7 : 1;
  int off = (h==0)? 0 : (h==1)? RROIS : 2*RROIS;
  int w = t>>5, lane = t&31;
  if (w < 4){
    const float* S = Y[w];
    for (int q=0;q<nq;q++){
      float s = 0.f;
      #pragma unroll
      for (int k=lane;k<FCH;k+=32) s += S[k]*w2[q*FCH+k];
      #pragma unroll
      for (int o2=16;o2;o2>>=1) s += __shfl_down_sync(0xffffffffu, s, o2);
      if (lane==0) out[off + (rb+w)*nq + q] = s + b2[q];
    }
  }
}

// ------------------------- launch -------------------------
extern "C" void kernel_launch(void* const* d_in, const int* in_sizes, int n_in,
                              void* d_out, int out_size){
  const float* xyz    = (const float*)d_in[0];
  const float* feat   = (const float*)d_in[1];
  const float* rois   = (const float*)d_in[2];
  const float* mlp_w0 = (const float*)d_in[3];
  const float* mlp_g0 = (const float*)d_in[4];
  const float* mlp_b0 = (const float*)d_in[5];
  const float* mlp_w1 = (const float*)d_in[6];
  const float* mlp_g1 = (const float*)d_in[7];
  const float* mlp_b1 = (const float*)d_in[8];
  const float* sw0    = (const float*)d_in[9];
  const float* sw1    = (const float*)d_in[10];
  const float* cw0    = (const float*)d_in[11];
  const float* cw1    = (const float*)d_in[12];
  const float* cw2    = (const float*)d_in[13];
  const float* cb2    = (const float*)d_in[14];
  const float* iw0    = (const float*)d_in[15];
  const float* iw1    = (const float*)d_in[16];
  const float* iw2    = (const float*)d_in[17];
  const float* ib2    = (const float*)d_in[18];
  const float* rw0    = (const float*)d_in[19];
  const float* rw1    = (const float*)d_in[20];
  const float* rw2    = (const float*)d_in[21];
  const float* rb2    = (const float*)d_in[22];
  float* out = (float*)d_out;

  cudaStream_t s2;
  cudaStreamCreateWithFlags(&s2, cudaStreamNonBlocking);
  cudaEvent_t eF, eA, eB;
  cudaEventCreateWithFlags(&eF, cudaEventDisableTiming);
  cudaEventCreateWithFlags(&eA, cudaEventDisableTiming);
  cudaEventCreateWithFlags(&eB, cudaEventDisableTiming);

  cudaEventRecord(eF, 0);
  cudaStreamWaitEvent(s2, eF, 0);
  k_pe   <<<1, 64, 0, s2>>>(mlp_w1, mlp_g1, mlp_b1, mlp_b0);
  k_prepA<<<896, 256, 0, s2>>>(sw0);
  cudaEventRecord(eA, s2);
  k_prepB<<<114, 256, 0, s2>>>(sw1, cw0, cw1, iw0, iw1, rw0, rw1);
  cudaEventRecord(eB, s2);

  // main stream: geometry chain (cellcnt invariant: all zero at entry)
  k_insert<<<161, 256>>>(xyz, rois);
  k_query <<<MGRID/32, 256>>>();
  k_mlp   <<<328, 256>>>(xyz, feat, mlp_w0, mlp_g0, mlp_b0, mlp_w1, mlp_g1, mlp_b1);

  cudaStreamWaitEvent(0, eA, 0);   // sh0g needs w0t + zeroed g_x + pe
  k_sh0g  <<<2*G3, 128>>>();
  cudaStreamWaitEvent(0, eB, 0);   // heads needs wT + base
  k_heads <<<dim3(RROIS/4, 3), 256>>>(cw2, cb2, iw2, ib2, rw2, rb2, out);
}

// round 17
// speedup vs baseline: 1.1342x; 1.1342x over previous
#include <cuda_runtime.h>
#include <math.h>

#define NPTS   8192
#define RROIS  128
#define G3     216
#define MGRID  (RROIS*G3)
#define NXC    252
#define NYC    252
#define NZC    11
#define NCELL  (NXC*NYC*NZC)
#define CAP    8
#define CMID   64
#define CIN    32
#define CK     35
#define FCH    256
#define GRID   444

// ------------------------- scratch -------------------------
__device__ int    g_cellcnt[NCELL];        // zero-init; reset each launch in phase 2
__device__ float4 g_cellpts[NCELL*CAP];
__device__ int    g_nsamp;
__device__ int    g_slist[MGRID*16];
__device__ int    g_gcnt[G3];
__device__ int    g_glist[G3*RROIS];
__device__ int    g_qidx[MGRID*16];
__device__ float  g_newxyz[MGRID*3];
__device__ float  g_delta[MGRID*CMID];
__device__ float  g_w0t[G3*CMID*FCH];
__device__ float  g_base[FCH];
__device__ float  g_pe[CMID];
__device__ float  g_x[RROIS*FCH];
__device__ float  g_wT[7*FCH*FCH];
__device__ int    g_barcnt;                // barrier arrivals (self-resetting)
__device__ volatile int g_barflag;         // sense flag (even #barriers -> ends at 0)

#define BN_INV 0.9999949932f

__device__ __forceinline__ int cellOf(int ix,int iy,int iz){ return (ix*NYC+iy)*NZC+iz; }

__device__ __forceinline__ void gridbar(int sense){
  __syncthreads();
  if (threadIdx.x == 0){
    __threadfence();
    if (atomicAdd(&g_barcnt, 1) == GRID-1){
      g_barcnt = 0;
      __threadfence();
      g_barflag = sense;
    } else {
      while (g_barflag != sense) __nanosleep(64);
    }
  }
  __syncthreads();
}

// ------------------------- the whole pipeline in one kernel -------------------------
__global__ void __launch_bounds__(256, 3) k_fused(
    const float* __restrict__ xyz,  const float* __restrict__ feat,
    const float* __restrict__ rois,
    const float* __restrict__ w0,   const float* __restrict__ gg0, const float* __restrict__ bb0,
    const float* __restrict__ w1,   const float* __restrict__ gg1, const float* __restrict__ bb1,
    const float* __restrict__ sw0,
    const float* __restrict__ m0,const float* __restrict__ m1,const float* __restrict__ m2,
    const float* __restrict__ m3,const float* __restrict__ m4,const float* __restrict__ m5,
    const float* __restrict__ m6,
    const float* __restrict__ cw2,const float* __restrict__ cb2,
    const float* __restrict__ iw2,const float* __restrict__ ib2,
    const float* __restrict__ rw2,const float* __restrict__ rb2,
    float* __restrict__ out){
  __shared__ __align__(16) unsigned char SB[33664];
  int tid = threadIdx.x;
  int bid = blockIdx.x;
  int tx = tid & 15, ty = tid >> 4;

  // ================= PHASE 0: insert + counters + grid-points + w0t transpose + zero g_x + pe =====
  for (int w = bid; w < 1058; w += GRID){
    __syncthreads();
    if (w < 32){
      int i = w*256 + tid;
      float x = xyz[3*i], y = xyz[3*i+1], z = xyz[3*i+2];
      int ix = (int)floorf((x+50.f)*2.5f); ix = min(max(ix,0), NXC-1);
      int iy = (int)floorf((y+50.f)*2.5f); iy = min(max(iy,0), NYC-1);
      int iz = (int)floorf((z+ 2.f)*2.5f); iz = min(max(iz,0), NZC-1);
      int cell = cellOf(ix,iy,iz);
      int slot = atomicAdd(&g_cellcnt[cell], 1);
      if (slot < CAP){
        float4 p; p.x=x; p.y=y; p.z=z; p.w=__int_as_float(i);
        g_cellpts[cell*CAP+slot] = p;
      }
    } else if (w == 32){
      if (tid < G3) g_gcnt[tid] = 0;
      if (tid == 255) g_nsamp = 0;
    } else if (w < 161){
      int r = w - 33;
      float*  R7  = (float*)SB;
      double* trg = (double*)(SB + 64);
      if (tid < 7) R7[tid] = rois[r*7+tid];
      if (tid == 7) trg[0] = cos((double)rois[r*7+6]);
      if (tid == 8) trg[1] = sin((double)rois[r*7+6]);
      __syncthreads();
      if (tid < G3){
        int m = r*G3 + tid;
        int ixg = tid/36, iyg = (tid/6)%6, izg = tid%6;
        float sx=R7[3], sy=R7[4], sz=R7[5];
        float lx = ((float)ixg + 0.5f)/6.0f * sx - 0.5f*sx;
        float ly = ((float)iyg + 0.5f)/6.0f * sy - 0.5f*sy;
        float lz = ((float)izg + 0.5f)/6.0f * sz - 0.5f*sz;
        float cs = (float)trg[0], sn = (float)trg[1];
        g_newxyz[3*m]   = lx*cs - ly*sn + R7[0];
        g_newxyz[3*m+1] = lx*sn + ly*cs + R7[1];
        g_newxyz[3*m+2] = lz + R7[2];
      }
    } else if (w < 1025){
      int b = w - 161;
      float* sh = (float*)SB;                  // 64*65 floats
      int ct = b % 216, ot = b / 216;
      int col0 = ct*64, o0 = ot*64;
      #pragma unroll
      for (int i=0;i<4;i++){
        int r = ty + 16*i;
        float4 v = *(const float4*)&sw0[(size_t)(o0+r)*13824 + col0 + 4*tx];
        float* t = &sh[r*65 + 4*tx];
        t[0]=v.x; t[1]=v.y; t[2]=v.z; t[3]=v.w;
      }
      __syncthreads();
      #pragma unroll
      for (int i=0;i<4;i++){
        int ci = ty + 16*i;
        int col = col0 + ci;
        int c = col / 216, g = col - c*216;
        float4 v;
        v.x = sh[(4*tx+0)*65 + ci];
        v.y = sh[(4*tx+1)*65 + ci];
        v.z = sh[(4*tx+2)*65 + ci];
        v.w = sh[(4*tx+3)*65 + ci];
        *(float4*)&g_w0t[(g*CMID + c)*FCH + o0 + 4*tx] = v;
      }
    } else if (w < 1057){
      int d = w - 1025;
      int4 z = make_int4(0,0,0,0);
      ((int4*)g_x)[d*256 + tid] = z;
    } else {
      float* h0e = (float*)SB;
      if (tid < 64) h0e[tid] = fmaxf(bb0[tid], 0.f);
      __syncthreads();
      if (tid < 64){
        float acc = 0.f;
        #pragma unroll 8
        for (int j=0;j<CMID;j++) acc += h0e[j]*w1[tid*CMID+j];
        g_pe[tid] = fmaxf(gg1[tid]*acc*BN_INV + bb1[tid], 0.f);
      }
    }
  }
  gridbar(1);

  // ================= PHASE 1: ball query + head-matrix pack + base =================
  for (int w = bid; w < 1232; w += GRID){
    __syncthreads();
    if (w < 864){
      int gw = w*32 + (tid >> 3);
      int l8 = tid & 7;
      unsigned mask8 = 0xFFu << (unsigned)(tid & 24);
      float px = g_newxyz[3*gw], py = g_newxyz[3*gw+1], pz = g_newxyz[3*gw+2];
      const float RS = 0.4001f;
      int ix0 = max((int)floorf((px-RS+50.f)*2.5f), 0);
      int ix1 = min((int)floorf((px+RS+50.f)*2.5f), NXC-1);
      int iy0 = max((int)floorf((py-RS+50.f)*2.5f), 0);
      int iy1 = min((int)floorf((py+RS+50.f)*2.5f), NYC-1);
      int iz0 = max((int)floorf((pz-RS+ 2.f)*2.5f), 0);
      int iz1 = min((int)floorf((pz+RS+ 2.f)*2.5f), NZC-1);
      int ny = iy1-iy0+1, nz = iz1-iz0+1;
      int ncl = (ix1-ix0+1)*ny*nz;

      int loc[16]; int nloc = 0;
      for (int cidx = l8; cidx < ncl; cidx += 8){
        int a   = cidx/(ny*nz);
        int rem = cidx - a*(ny*nz);
        int cix = ix0 + a;
        int ciy = iy0 + rem/nz;
        int ciz = iz0 + rem - (rem/nz)*nz;
        int cell = cellOf(cix,ciy,ciz);
        int c = min(g_cellcnt[cell], CAP);
        const float4* cp = &g_cellpts[cell*CAP];
        for (int u=0; u<c; u++){
          float4 p = cp[u];
          float dx = p.x-px, dy = p.y-py, dz = p.z-pz;
          if (dx*dx + dy*dy + dz*dz < 0.16f){
            int j = __float_as_int(p.w);
            if (nloc < 16){
              int q = nloc++;
              while (q>0 && loc[q-1]>j){ loc[q]=loc[q-1]; q--; }
              loc[q] = j;
            } else if (j < loc[15]){
              int q = 15;
              while (q>0 && loc[q-1]>j){ loc[q]=loc[q-1]; q--; }
              loc[q] = j;
            }
          }
        }
      }
      unsigned hits = __ballot_sync(0xffffffffu, nloc > 0) & mask8;
      if (hits != 0){
        int ptr = 0;
        int head = (nloc > 0) ? loc[0] : 0x7fffffff;
        int cnt = 0;
        #pragma unroll 1
        for (int it=0; it<16; it++){
          int mn = __reduce_min_sync(mask8, head);
          if (mn == 0x7fffffff) break;
          if (l8 == 0) g_qidx[gw*16 + cnt] = mn;
          cnt++;
          if (head == mn){
            ptr++;
            head = (ptr < nloc) ? loc[ptr] : 0x7fffffff;
          }
        }
        int base = 0;
        if (l8 == 0){
          int gi = gw % G3, r = gw / G3;
          int s = atomicAdd(&g_gcnt[gi], 1); g_glist[gi*RROIS+s] = r;
          base = atomicAdd(&g_nsamp, cnt);
        }
        base = __shfl_sync(mask8, base, (tid & 24));
        for (int s=l8; s<cnt; s+=8) g_slist[base+s] = gw*16+s;
        for (int c=l8; c<CMID; c+=8) g_delta[gw*CMID+c] = 0.f;
      }
    } else if (w < 976){
      int b = w - 864;
      float* sh = (float*)SB;
      int mat = b >> 4, tt = b & 15;
      int kt = tt & 3, ot = tt >> 2;
      const float* W = (mat==0)?m0:(mat==1)?m1:(mat==2)?m2:(mat==3)?m3:(mat==4)?m4:(mat==5)?m5:m6;
      int k0 = kt*64, o0 = ot*64;
      #pragma unroll
      for (int i=0;i<4;i++){
        int r = ty + 16*i;
        float4 v = *(const float4*)&W[(o0+r)*FCH + k0 + 4*tx];
        float* t = &sh[r*65 + 4*tx];
        t[0]=v.x; t[1]=v.y; t[2]=v.z; t[3]=v.w;
      }
      __syncthreads();
      #pragma unroll
      for (int i=0;i<4;i++){
        int idx = tid + 256*i;
        int ol = idx & 63, k4l = idx >> 6;
        float4 v;
        v.x = sh[ol*65 + 4*k4l+0];
        v.y = sh[ol*65 + 4*k4l+1];
        v.z = sh[ol*65 + 4*k4l+2];
        v.w = sh[ol*65 + 4*k4l+3];
        int k4g = (k0>>2) + k4l;
        *(float4*)&g_wT[mat*FCH*FCH + k4g*1024 + (o0+ol)*4] = v;
      }
    } else {
      int o = w - 976;
      float* spe = (float*)SB;          // 64
      float* red = (float*)(SB + 256);  // 256
      if (tid < 64) spe[tid] = g_pe[tid];
      __syncthreads();
      float s = 0.f;
      const float4* row4 = (const float4*)&sw0[(size_t)o*13824];
      for (int it=tid; it<3456; it+=256){
        float4 v = row4[it];
        int col = it*4;
        int c0 = col/216; int rem = col - c0*216;
        float p0 = spe[c0];
        float p1 = spe[(rem+1>=216)? c0+1 : c0];
        float p2 = spe[(rem+2>=216)? c0+1 : c0];
        float p3 = spe[(rem+3>=216)? c0+1 : c0];
        s += v.x*p0 + v.y*p1 + v.z*p2 + v.w*p3;
      }
      red[tid] = s; __syncthreads();
      if (tid<128) red[tid] += red[tid+128]; __syncthreads();
      if (tid<64)  red[tid] += red[tid+64];  __syncthreads();
      if (tid<32){
        float v = red[tid] + red[tid+32];
        #pragma unroll
        for (int off=16;off;off>>=1) v += __shfl_down_sync(0xffffffffu, v, off);
        if (tid==0) g_base[o] = v;
      }
    }
  }
  gridbar(0);

  // ================= PHASE 2: cellcnt reset + point MLP (warp per sample) =================
  if (bid < 32){
    int i = bid*256 + tid;
    float x = xyz[3*i], y = xyz[3*i+1], z = xyz[3*i+2];
    int ix = (int)floorf((x+50.f)*2.5f); ix = min(max(ix,0), NXC-1);
    int iy = (int)floorf((y+50.f)*2.5f); iy = min(max(iy,0), NYC-1);
    int iz = (int)floorf((z+ 2.f)*2.5f); iz = min(max(iz,0), NZC-1);
    g_cellcnt[cellOf(ix,iy,iz)] = 0;
  }
  {
    float* sw0s = (float*)SB;              // 2240
    float* sw1s = (float*)(SB + 8960);     // 4160 (stride 65)
    float* sg0  = (float*)(SB + 25600);
    float* sb0  = (float*)(SB + 25856);
    float* sg1  = (float*)(SB + 26112);
    float* sb1  = (float*)(SB + 26368);
    const float4* w04 = (const float4*)w0;
    for (int e=tid; e<560; e+=256) ((float4*)sw0s)[e] = w04[e];
    const float4* w14 = (const float4*)w1;
    for (int e=tid; e<1024; e+=256){
      float4 v = w14[e];
      int c = e>>4, j0 = (e&15)*4;
      float* p = &sw1s[c*65 + j0];
      p[0]=v.x; p[1]=v.y; p[2]=v.z; p[3]=v.w;
    }
    if (tid < 64){
      sg0[tid]=gg0[tid]; sb0[tid]=bb0[tid]; sg1[tid]=gg1[tid]; sb1[tid]=bb1[tid];
    }
    __syncthreads();
    int wid = tid >> 5, lane = tid & 31;
    int ch0 = lane, ch1 = lane + 32;
    float g0a=sg0[ch0], b0a=sb0[ch0], g0b=sg0[ch1], b0b=sb0[ch1];
    float g1a=sg1[ch0], b1a=sb1[ch0], g1b=sg1[ch1], b1b=sb1[ch1];
    int nsamp = g_nsamp;
    for (int p = bid*8 + wid; p < nsamp; p += GRID*8){
      int e = g_slist[p];
      int m = e >> 4;
      int j = g_qidx[e];
      float nx=g_newxyz[3*m], ny=g_newxyz[3*m+1], nz=g_newxyz[3*m+2];
      float v, ve = 0.f;
      if (lane < 3) v = xyz[3*j+lane] - ((lane==0)?nx:((lane==1)?ny:nz));
      else          v = feat[j*CIN + lane-3];
      if (lane < 3) ve = feat[j*CIN + 29 + lane];
      float a0=0.f, a1=0.f;
      #pragma unroll
      for (int k=0;k<32;k++){
        float x = __shfl_sync(0xffffffffu, v, k);
        a0 += x*sw0s[ch0*CK+k];
        a1 += x*sw0s[ch1*CK+k];
      }
      #pragma unroll
      for (int k=0;k<3;k++){
        float x = __shfl_sync(0xffffffffu, ve, k);
        a0 += x*sw0s[ch0*CK+32+k];
        a1 += x*sw0s[ch1*CK+32+k];
      }
      float h0a = fmaxf(g0a*a0*BN_INV + b0a, 0.f);
      float h0b = fmaxf(g0b*a1*BN_INV + b0b, 0.f);
      float c0=0.f, c1=0.f;
      #pragma unroll
      for (int jj=0;jj<32;jj++){
        float hv = __shfl_sync(0xffffffffu, h0a, jj);
        c0 += hv*sw1s[ch0*65+jj];
        c1 += hv*sw1s[ch1*65+jj];
      }
      #pragma unroll
      for (int jj=0;jj<32;jj++){
        float hv = __shfl_sync(0xffffffffu, h0b, jj);
        c0 += hv*sw1s[ch0*65+32+jj];
        c1 += hv*sw1s[ch1*65+32+jj];
      }
      float o0 = fmaxf(g1a*c0*BN_INV + b1a, 0.f);
      float o1 = fmaxf(g1b*c1*BN_INV + b1b, 0.f);
      atomicMax((unsigned*)g_delta + (m*CMID + ch0), __float_as_uint(o0));
      atomicMax((unsigned*)g_delta + (m*CMID + ch1), __float_as_uint(o1));
    }
  }
  gridbar(1);

  // ================= PHASE 3: sparse scatter =================
  for (int w = bid; w < 2*G3; w += GRID){
    __syncthreads();
    int g = w >> 1, half = w & 1;
    int ng = g_gcnt[g];
    if (ng == 0) continue;
    float* sw  = (float*)SB;               // 8192 floats
    float* sd0 = (float*)(SB + 32768);
    float* sd1 = (float*)(SB + 33024);
    float* spe = (float*)(SB + 33280);
    const float4* s4 = (const float4*)g_w0t;
    float4* sw4 = (float4*)sw;
    for (int i=tid; i<2048; i+=256){
      int c = i >> 5, o4 = i & 31;
      sw4[c*32 + o4] = s4[(size_t)(g*CMID + c)*64 + half*32 + o4];
    }
    if (tid < CMID) spe[tid] = g_pe[tid];
    __syncthreads();
    int o = half*128 + (tid & 127);
    for (int t=0; t<ng; t+=2){
      int r0 = g_glist[g*RROIS + t];
      int r1 = (t+1<ng)? g_glist[g*RROIS + t+1] : -1;
      if (tid < CMID)                      sd0[tid]    = g_delta[(r0*G3+g)*CMID + tid]    - spe[tid];
      else if (tid < 2*CMID && r1 >= 0)    sd1[tid-64] = g_delta[(r1*G3+g)*CMID + tid-64] - spe[tid-64];
      __syncthreads();
      if (tid < 128){
        float a0 = 0.f, a1 = 0.f;
        #pragma unroll 16
        for (int c=0;c<CMID;c++){
          float wv = sw[c*128 + tid];
          a0 += sd0[c]*wv;
          a1 += sd1[c]*wv;
        }
        atomicAdd(&g_x[r0*FCH + o], a0);
        if (r1 >= 0) atomicAdd(&g_x[r1*FCH + o], a1);
      }
      __syncthreads();
    }
  }
  gridbar(0);

  // ================= PHASE 4: head MLPs =================
  for (int w = bid; w < 96; w += GRID){
    float (*X)[FCH] = (float(*)[FCH])SB;
    float (*Y)[FCH] = (float(*)[FCH])(SB + 4096*4);
    int rb = (w & 31)*4, h = w >> 5;
    float base = g_base[tid];
    #pragma unroll
    for (int rr=0; rr<4; rr++) X[rr][tid] = fmaxf(g_x[(rb+rr)*FCH + tid] + base, 0.f);
    __syncthreads();
    for (int L=0; L<3; L++){
      int mat = (L==0)? 0 : (L + 2*h);
      const float4* P  = (const float4*)&g_wT[mat*FCH*FCH];
      const float4* x0 = (const float4*)X[0];
      const float4* x1 = (const float4*)X[1];
      const float4* x2 = (const float4*)X[2];
      const float4* x3 = (const float4*)X[3];
      float a0=0.f,a1=0.f,a2=0.f,a3=0.f;
      #pragma unroll 8
      for (int k4=0;k4<64;k4++){
        float4 ww = P[k4*FCH + tid];
        float4 v0=x0[k4], v1=x1[k4], v2=x2[k4], v3=x3[k4];
        a0 += ww.x*v0.x + ww.y*v0.y + ww.z*v0.z + ww.w*v0.w;
        a1 += ww.x*v1.x + ww.y*v1.y + ww.z*v1.z + ww.w*v1.w;
        a2 += ww.x*v2.x + ww.y*v2.y + ww.z*v2.z + ww.w*v2.w;
        a3 += ww.x*v3.x + ww.y*v3.y + ww.z*v3.z + ww.w*v3.w;
      }
      Y[0][tid]=fmaxf(a0,0.f); Y[1][tid]=fmaxf(a1,0.f);
      Y[2][tid]=fmaxf(a2,0.f); Y[3][tid]=fmaxf(a3,0.f);
      __syncthreads();
      // swap X and Y
      float (*T)[FCH] = X; X = Y; Y = T;
    }
    const float* w2 = (h==0)? cw2 : (h==1)? iw2 : rw2;
    const float* b2 = (h==0)? cb2 : (h==1)? ib2 : rb2;
    int nq  = (h==2)? 7 : 1;
    int off = (h==0)? 0 : (h==1)? RROIS : 2*RROIS;
    int wrp = tid>>5, lane = tid&31;
    if (wrp < 4){
      const float* S = X[wrp];   // result after 3 layers
      for (int q=0;q<nq;q++){
        float s = 0.f;
        #pragma unroll
        for (int k=lane;k<FCH;k+=32) s += S[k]*w2[q*FCH+k];
        #pragma unroll
        for (int o2=16;o2;o2>>=1) s += __shfl_down_sync(0xffffffffu, s, o2);
        if (lane==0) out[off + (rb+wrp)*nq + q] = s + b2[q];
      }
    }
    __syncthreads();
  }
}

// ------------------------- launch -------------------------
extern "C" void kernel_launch(void* const* d_in, const int* in_sizes, int n_in,
                              void* d_out, int out_size){
  const float* xyz    = (const float*)d_in[0];
  const float* feat   = (const float*)d_in[1];
  const float* rois   = (const float*)d_in[2];
  const float* mlp_w0 = (const float*)d_in[3];
  const float* mlp_g0 = (const float*)d_in[4];
  const float* mlp_b0 = (const float*)d_in[5];
  const float* mlp_w1 = (const float*)d_in[6];
  const float* mlp_g1 = (const float*)d_in[7];
  const float* mlp_b1 = (const float*)d_in[8];
  const float* sw0    = (const float*)d_in[9];
  const float* sw1    = (const float*)d_in[10];
  const float* cw0    = (const float*)d_in[11];
  const float* cw1    = (const float*)d_in[12];
  const float* cw2    = (const float*)d_in[13];
  const float* cb2    = (const float*)d_in[14];
  const float* iw0    = (const float*)d_in[15];
  const float* iw1    = (const float*)d_in[16];
  const float* iw2    = (const float*)d_in[17];
  const float* ib2    = (const float*)d_in[18];
  const float* rw0    = (const float*)d_in[19];
  const float* rw1    = (const float*)d_in[20];
  const float* rw2    = (const float*)d_in[21];
  const float* rb2    = (const float*)d_in[22];
  float* out = (float*)d_out;

  k_fused<<<GRID, 256>>>(xyz, feat, rois,
                         mlp_w0, mlp_g0, mlp_b0, mlp_w1, mlp_g1, mlp_b1,
                         sw0, sw1, cw0, cw1, iw0, iw1, rw0, rw1,
                         cw2, cb2, iw2, ib2, rw2, rb2, out);
}